// round 14
// baseline (speedup 1.0000x reference)
#include <cuda_runtime.h>
#include <cuda_bf16.h>
#include <cuda_fp16.h>
#include <cstdint>
#include <math.h>

#define T_DIM 128
#define B_DIM 512
#define N_DIM 256
#define M_DIM 512
#define G_DIM 2048   // 4*M
#define K_GATES 768  // N + M
#define SPAD 36      // smem row stride for tf32 kernels
#define HCPAD 36     // stride for epilogue hc/We tiles (float4-aligned)

// ---------------- device scratch (no allocation allowed) ----------------
__device__ __half g_UeX[B_DIM * T_DIM * N_DIM];     // [b][s][n]  33.5 MB (fp16)
__device__ float g_hbuf[2][B_DIM * M_DIM];          // double-buffered h
__device__ float g_cbuf[2][B_DIM * M_DIM];          // double-buffered c
__device__ float g_hseq[T_DIM * B_DIM * M_DIM];     // 134 MB
__device__ float g_xt[B_DIM * N_DIM];               // x_tilde
__device__ float g_wepart[32 * B_DIM * T_DIM];      // split-K partials for we (8 MB)
__device__ float g_part[(T_DIM * B_DIM) * 16];      // per-(colblock,warp) row sums
__device__ float g_l[B_DIM * T_DIM];                // attention logits l

// ---------------- fast math helpers ----------------
__device__ __forceinline__ float tanh_fast(float x) {
    float y;
    asm("tanh.approx.f32 %0, %1;" : "=f"(y) : "f"(x));
    return y;
}
__device__ __forceinline__ float sigmoid_fast(float x) {
    return 0.5f * tanh_fast(0.5f * x) + 0.5f;
}

// ---------------- tf32 mma helpers ----------------
__device__ __forceinline__ void tf32_split(float v, uint32_t& hi, uint32_t& lo) {
    asm("cvt.rna.tf32.f32 %0, %1;" : "=r"(hi) : "f"(v));
    float r = v - __uint_as_float(hi);
    asm("cvt.rna.tf32.f32 %0, %1;" : "=r"(lo) : "f"(r));
}
__device__ __forceinline__ uint32_t tf32_hi(float v) {
    uint32_t hi;
    asm("cvt.rna.tf32.f32 %0, %1;" : "=r"(hi) : "f"(v));
    return hi;
}
__device__ __forceinline__ void mma_tf32(float* c, const uint32_t* a, const uint32_t* b) {
    asm volatile(
        "mma.sync.aligned.m16n8k8.row.col.f32.tf32.tf32.f32 "
        "{%0,%1,%2,%3}, {%4,%5,%6,%7}, {%8,%9}, {%0,%1,%2,%3};\n"
        : "+f"(c[0]), "+f"(c[1]), "+f"(c[2]), "+f"(c[3])
        : "r"(a[0]), "r"(a[1]), "r"(a[2]), "r"(a[3]), "r"(b[0]), "r"(b[1]));
}

// ---------------- init h,c into buffer 0 ----------------
__global__ void k_init(const float* __restrict__ h0, const float* __restrict__ c0) {
    int idx = blockIdx.x * blockDim.x + threadIdx.x;
    g_hbuf[0][idx] = h0[idx];
    g_cbuf[0][idx] = c0[idx];
}

// ---------------- Ue_x[b][s][n] (fp16 out) ----------------
__global__ void k_ue(const float* __restrict__ x, const float* __restrict__ Ue_w,
                     const float* __restrict__ Ue_b) {
    __shared__ float xs[T_DIM][64];
    int b = blockIdx.x;
    int n0 = blockIdx.y * 64;
    int tid = threadIdx.x;
    for (int idx = tid; idx < T_DIM * 64; idx += 256) {
        int t = idx >> 6, n = idx & 63;
        xs[t][n] = x[(size_t)t * B_DIM * N_DIM + b * N_DIM + n0 + n];
    }
    __syncthreads();
    for (int r = 0; r < 32; r++) {
        int o = tid + 256 * r;
        int s = o >> 6, n = o & 63;
        float acc = Ue_b[s];
        const float* uw = Ue_w + s * T_DIM;
        #pragma unroll 8
        for (int t = 0; t < T_DIM; t++) acc += xs[t][n] * uw[t];
        g_UeX[(b * T_DIM + s) * N_DIM + n0 + n] = __float2half_rn(acc);
    }
}

// ---------------- k_we (PROLOGUE ONLY, t=0): 8-slice split-K for we from h0,c0 ----
__global__ void __launch_bounds__(256) k_we(const float* __restrict__ We_w) {
    __shared__ float As[16][68];
    __shared__ float Bs[16][68];
    int cb = blockIdx.x, rb = blockIdx.y, kc = blockIdx.z;
    int tid = threadIdx.x;
    int tx = tid & 15, ty = tid >> 4;
    int kl = tid & 15, il = tid >> 4;
    int row0 = rb * 64, col0 = cb * 64;
    const float* src = (kc < 4) ? (g_hbuf[0] + kc * 128) : (g_cbuf[0] + (kc - 4) * 128);
    const float* wsrc = We_w + kc * 128;
    float acc[4][4] = {};
    for (int k0 = 0; k0 < 128; k0 += 16) {
        int k = k0 + kl;
        #pragma unroll
        for (int s = 0; s < 4; s++) {
            int i = il + s * 16;
            As[kl][i] = src[(size_t)(row0 + i) * M_DIM + k];
            Bs[kl][i] = wsrc[(size_t)(col0 + i) * 1024 + k];
        }
        __syncthreads();
        #pragma unroll
        for (int kk = 0; kk < 16; kk++) {
            float4 a4 = *(const float4*)&As[kk][ty * 4];
            float4 b4 = *(const float4*)&Bs[kk][tx * 4];
            float av[4] = {a4.x, a4.y, a4.z, a4.w};
            float bv[4] = {b4.x, b4.y, b4.z, b4.w};
            #pragma unroll
            for (int ii = 0; ii < 4; ii++)
                #pragma unroll
                for (int jj = 0; jj < 4; jj++) acc[ii][jj] += av[ii] * bv[jj];
        }
        __syncthreads();
    }
    #pragma unroll
    for (int ii = 0; ii < 4; ii++) {
        int row = row0 + ty * 4 + ii;
        #pragma unroll
        for (int jj = 0; jj < 4; jj++) {
            int s = col0 + tx * 4 + jj;
            g_wepart[(kc * B_DIM + row) * T_DIM + s] = acc[ii][jj];
        }
    }
}

// ---------------- k_e: 512 threads, s split 4-way, half2 loads -----------------
__global__ void __launch_bounds__(512) k_e(int t, const float* __restrict__ x,
                    const float* __restrict__ We_b,
                    const float* __restrict__ ve_w, const float* __restrict__ ve_b) {
    __shared__ float s_we[T_DIM];
    __shared__ float s_ve[T_DIM];
    __shared__ float s_part[4 * N_DIM];
    __shared__ float red[256];
    int b = blockIdx.x;
    int tid = threadIdx.x;
    int ns = (t == 0) ? 8 : 32;
    if (tid < T_DIM) {
        float w = We_b[tid];
        for (int kc = 0; kc < ns; kc++)
            w += g_wepart[(kc * B_DIM + b) * T_DIM + tid];
        s_we[tid] = w;
        s_ve[tid] = ve_w[tid];
    }
    __syncthreads();

    int np = tid & 127;
    int sq = tid >> 7;
    const __half2* ue = (const __half2*)(g_UeX + ((size_t)b * T_DIM + sq * 32) * N_DIM) + np;
    float acc0 = 0.0f, acc1 = 0.0f;
    #pragma unroll
    for (int s0 = 0; s0 < 32; s0 += 8) {
        __half2 v[8];
        #pragma unroll
        for (int u = 0; u < 8; u++) v[u] = __ldg(ue + (size_t)(s0 + u) * (N_DIM / 2));
        #pragma unroll
        for (int u = 0; u < 8; u++) {
            int s = sq * 32 + s0 + u;
            float2 f = __half22float2(v[u]);
            float wes = s_we[s], ves = s_ve[s];
            acc0 += tanh_fast(wes + f.x) * ves;
            acc1 += tanh_fast(wes + f.y) * ves;
        }
    }
    *(float2*)&s_part[sq * N_DIM + 2 * np] = make_float2(acc0, acc1);
    __syncthreads();

    float e = 0.0f;
    if (tid < N_DIM) {
        e = ve_b[0];
        #pragma unroll
        for (int q = 0; q < 4; q++) e += s_part[q * N_DIM + tid];
        red[tid] = e;
    }
    __syncthreads();
    for (int o = 128; o >= 32; o >>= 1) {
        if (tid < o) red[tid] = fmaxf(red[tid], red[tid + o]);
        __syncthreads();
    }
    if (tid < 32) {
        float v = red[tid];
        #pragma unroll
        for (int o = 16; o; o >>= 1) v = fmaxf(v, __shfl_xor_sync(0xffffffffu, v, o));
        red[tid] = v;
    }
    __syncthreads();
    float mx = red[0];
    float ev = 0.0f;
    __syncthreads();
    if (tid < N_DIM) {
        ev = __expf(e - mx);
        red[tid] = ev;
    }
    __syncthreads();
    for (int o = 128; o >= 32; o >>= 1) {
        if (tid < o) red[tid] += red[tid + o];
        __syncthreads();
    }
    if (tid < 32) {
        float v = red[tid];
        #pragma unroll
        for (int o = 16; o; o >>= 1) v += __shfl_xor_sync(0xffffffffu, v, o);
        red[tid] = v;
    }
    __syncthreads();
    if (tid < N_DIM) {
        float alpha = ev / red[0];
        g_xt[b * N_DIM + tid] = alpha * x[(size_t)t * B_DIM * N_DIM + b * N_DIM + tid];
    }
}

// ---------------- k_gatescell: 64-row blocks for 2x parallelism ------------------
// grid (32, 8) = 256 blocks. Block (cb, by): 64 batch rows x 64 gate cols (16 m).
// 8 warps as (wm 2 x wn 4), warp tile 32 rows x 16 cols. Fused cell + we-partial.
__global__ void __launch_bounds__(256) k_gatescell(int t,
        const float* __restrict__ Wih, const float* __restrict__ Whh,
        const float* __restrict__ b_ih, const float* __restrict__ b_hh,
        const float* __restrict__ We_w) {
    __shared__ float pool[7040];   // max phase: s_hc 64*36 + s_We 128*36 = 6912
    float* As = pool;              // 64*36 = 2304
    float* Bs = pool + 64 * SPAD;  // 64*36 = 2304
    int in = t & 1, ob = in ^ 1;
    const float* hin = g_hbuf[in];
    const float* cin = g_cbuf[in];
    float* hout = g_hbuf[ob];
    float* cout = g_cbuf[ob];
    int tid = threadIdx.x;
    int w = tid >> 5, lane = tid & 31;
    int g = lane >> 2, tig = lane & 3;
    int wm = w & 1, wn = w >> 1;
    int cb = blockIdx.x;
    int m0 = blockIdx.y * 64;
    int r = tid >> 3, kq = (tid & 7) * 4;   // r: 0..31
    float c[2][2][4] = {};

    for (int k0 = 0; k0 < K_GATES; k0 += 32) {
        const float* asrc; int astride;
        if (k0 < N_DIM) { asrc = g_xt + k0; astride = N_DIM; }
        else            { asrc = hin + (k0 - N_DIM); astride = M_DIM; }
        #pragma unroll
        for (int i = 0; i < 2; i++) {
            int row = r + 32 * i;
            *(float4*)&As[row * SPAD + kq] =
                *(const float4*)(asrc + (size_t)(m0 + row) * astride + kq);
        }
        #pragma unroll
        for (int i2 = 0; i2 < 2; i2++) {
            int i = r + 32 * i2;
            int j = (i & 3) * M_DIM + cb * 16 + (i >> 2);
            const float* bp = (k0 < N_DIM) ? (Wih + (size_t)j * N_DIM + k0)
                                           : (Whh + (size_t)j * M_DIM + (k0 - N_DIM));
            *(float4*)&Bs[i * SPAD + kq] = *(const float4*)(bp + kq);
        }
        __syncthreads();
        #pragma unroll
        for (int kt = 0; kt < 4; kt++) {
            int kk = kt * 8 + tig;
            uint32_t ahi[2][4], alo[2][4], bhi[2][2], blo[2][2];
            #pragma unroll
            for (int mt = 0; mt < 2; mt++) {
                int rb = wm * 32 + mt * 16 + g;
                tf32_split(As[rb * SPAD + kk],           ahi[mt][0], alo[mt][0]);
                tf32_split(As[(rb + 8) * SPAD + kk],     ahi[mt][1], alo[mt][1]);
                tf32_split(As[rb * SPAD + kk + 4],       ahi[mt][2], alo[mt][2]);
                tf32_split(As[(rb + 8) * SPAD + kk + 4], ahi[mt][3], alo[mt][3]);
            }
            #pragma unroll
            for (int nt = 0; nt < 2; nt++) {
                int nb = wn * 16 + nt * 8 + g;
                tf32_split(Bs[nb * SPAD + kk],     bhi[nt][0], blo[nt][0]);
                tf32_split(Bs[nb * SPAD + kk + 4], bhi[nt][1], blo[nt][1]);
            }
            #pragma unroll
            for (int mt = 0; mt < 2; mt++)
                #pragma unroll
                for (int nt = 0; nt < 2; nt++) {
                    mma_tf32(c[mt][nt], ahi[mt], bhi[nt]);
                    mma_tf32(c[mt][nt], ahi[mt], blo[nt]);
                    mma_tf32(c[mt][nt], alo[mt], bhi[nt]);
                }
        }
        __syncthreads();
    }

    // stage accumulators: pool[row][68], 64 rows
    #pragma unroll
    for (int mt = 0; mt < 2; mt++) {
        int rl = wm * 32 + mt * 16 + g;
        #pragma unroll
        for (int nt = 0; nt < 2; nt++) {
            int qd = wn * 16 + nt * 8 + tig * 2;
            pool[rl * 68 + qd]           = c[mt][nt][0];
            pool[rl * 68 + qd + 1]       = c[mt][nt][1];
            pool[(rl + 8) * 68 + qd]     = c[mt][nt][2];
            pool[(rl + 8) * 68 + qd + 1] = c[mt][nt][3];
        }
    }
    __syncthreads();

    // cell: 64 rows x 16 m = 1024 cells, 4 per thread
    float hnv[4], cnv[4];
    #pragma unroll
    for (int u = 0; u < 4; u++) {
        int idx = tid + 256 * u;
        int rl = idx >> 4, ml = idx & 15;
        int b = m0 + rl;
        int m = cb * 16 + ml;
        float gi = pool[rl * 68 + ml * 4 + 0] + b_ih[m]             + b_hh[m];
        float gf = pool[rl * 68 + ml * 4 + 1] + b_ih[M_DIM + m]     + b_hh[M_DIM + m];
        float gg = pool[rl * 68 + ml * 4 + 2] + b_ih[2 * M_DIM + m] + b_hh[2 * M_DIM + m];
        float go = pool[rl * 68 + ml * 4 + 3] + b_ih[3 * M_DIM + m] + b_hh[3 * M_DIM + m];
        float cprev = cin[(size_t)b * M_DIM + m];
        float si = sigmoid_fast(gi);
        float sf = sigmoid_fast(gf);
        float tg = tanh_fast(gg);
        float so = sigmoid_fast(go);
        float cn = sf * cprev + si * tg;
        float hn = so * tanh_fast(cn);
        cout[(size_t)b * M_DIM + m] = cn;
        hout[(size_t)b * M_DIM + m] = hn;
        g_hseq[(size_t)t * B_DIM * M_DIM + (size_t)b * M_DIM + m] = hn;
        hnv[u] = hn;
        cnv[u] = cn;
    }
    __syncthreads();

    if (t == T_DIM - 1) return;

    // we-partial epilogue: rows 64, slice cb (32 k = 16 h + 16 c)
    float* s_hc = pool;                    // 64*36
    float* s_We = pool + 64 * HCPAD;       // 128*36
    #pragma unroll
    for (int u = 0; u < 4; u++) {
        int idx = tid + 256 * u;
        int rl = idx >> 4, ml = idx & 15;
        s_hc[rl * HCPAD + ml]      = hnv[u];
        s_hc[rl * HCPAD + 16 + ml] = cnv[u];
    }
    for (int i = tid; i < 128 * 16; i += 256) {
        int s = i >> 4, kh = i & 15;
        s_We[s * HCPAD + kh]      = We_w[(size_t)s * 1024 + cb * 16 + kh];
        s_We[s * HCPAD + 16 + kh] = We_w[(size_t)s * 1024 + 512 + cb * 16 + kh];
    }
    __syncthreads();

    int tx = tid & 15, ty4 = tid >> 4;
    #pragma unroll
    for (int sub = 0; sub < 2; sub++) {
        int s0 = sub * 64;
        float acc[4][4] = {};
        #pragma unroll
        for (int kk = 0; kk < 32; kk += 4) {
            float4 a4[4], b4[4];
            #pragma unroll
            for (int ii = 0; ii < 4; ii++)
                a4[ii] = *(const float4*)&s_hc[(ty4 * 4 + ii) * HCPAD + kk];
            #pragma unroll
            for (int jj = 0; jj < 4; jj++)
                b4[jj] = *(const float4*)&s_We[(s0 + tx * 4 + jj) * HCPAD + kk];
            #pragma unroll
            for (int ii = 0; ii < 4; ii++) {
                float av[4] = {a4[ii].x, a4[ii].y, a4[ii].z, a4[ii].w};
                #pragma unroll
                for (int jj = 0; jj < 4; jj++) {
                    acc[ii][jj] += av[0] * b4[jj].x + av[1] * b4[jj].y
                                 + av[2] * b4[jj].z + av[3] * b4[jj].w;
                }
            }
        }
        #pragma unroll
        for (int ii = 0; ii < 4; ii++) {
            int row = m0 + ty4 * 4 + ii;
            #pragma unroll
            for (int jj = 0; jj < 4; jj++)
                g_wepart[(cb * B_DIM + row) * T_DIM + s0 + tx * 4 + jj] = acc[ii][jj];
        }
    }
}

// ---------------- k_ud (tf32 2-term mma) ----------------
__global__ void __launch_bounds__(256) k_ud(
        const float* __restrict__ Ud_w, const float* __restrict__ Ud_b,
        const float* __restrict__ vd_w) {
    __shared__ float As[128 * SPAD];
    __shared__ float Bs[64 * SPAD];
    int tid = threadIdx.x;
    int w = tid >> 5, lane = tid & 31;
    int g = lane >> 2, tig = lane & 3;
    int wm = w & 3, wn = w >> 2;
    int m0 = blockIdx.y * 128, n0 = blockIdx.x * 64;
    int r = tid >> 3, kq = (tid & 7) * 4;
    float c[2][4][4] = {};

    for (int k0 = 0; k0 < M_DIM; k0 += 32) {
        #pragma unroll
        for (int i = 0; i < 4; i++) {
            int row = r + 32 * i;
            *(float4*)&As[row * SPAD + kq] =
                *(const float4*)(g_hseq + (size_t)(m0 + row) * M_DIM + k0 + kq);
        }
        #pragma unroll
        for (int i = 0; i < 2; i++) {
            int row = r + 32 * i;
            *(float4*)&Bs[row * SPAD + kq] =
                *(const float4*)(Ud_w + (size_t)(n0 + row) * M_DIM + k0 + kq);
        }
        __syncthreads();
        #pragma unroll
        for (int kt = 0; kt < 4; kt++) {
            int kk = kt * 8 + tig;
            uint32_t ahi[2][4], alo[2][4], bhi[4][2];
            #pragma unroll
            for (int mt = 0; mt < 2; mt++) {
                int rb = wm * 32 + mt * 16 + g;
                tf32_split(As[rb * SPAD + kk],           ahi[mt][0], alo[mt][0]);
                tf32_split(As[(rb + 8) * SPAD + kk],     ahi[mt][1], alo[mt][1]);
                tf32_split(As[rb * SPAD + kk + 4],       ahi[mt][2], alo[mt][2]);
                tf32_split(As[(rb + 8) * SPAD + kk + 4], ahi[mt][3], alo[mt][3]);
            }
            #pragma unroll
            for (int nt = 0; nt < 4; nt++) {
                int nb = wn * 32 + nt * 8 + g;
                bhi[nt][0] = tf32_hi(Bs[nb * SPAD + kk]);
                bhi[nt][1] = tf32_hi(Bs[nb * SPAD + kk + 4]);
            }
            #pragma unroll
            for (int mt = 0; mt < 2; mt++)
                #pragma unroll
                for (int nt = 0; nt < 4; nt++) {
                    mma_tf32(c[mt][nt], ahi[mt], bhi[nt]);
                    mma_tf32(c[mt][nt], alo[mt], bhi[nt]);
                }
        }
        __syncthreads();
    }
    #pragma unroll
    for (int mt = 0; mt < 2; mt++) {
        float rs0 = 0.0f, rs8 = 0.0f;
        #pragma unroll
        for (int nt = 0; nt < 4; nt++) {
            int j0 = n0 + wn * 32 + nt * 8 + tig * 2;
            float w0 = vd_w[j0], w1 = vd_w[j0 + 1];
            float d0 = Ud_b[j0], d1 = Ud_b[j0 + 1];
            rs0 += tanh_fast(c[mt][nt][0] + d0) * w0 + tanh_fast(c[mt][nt][1] + d1) * w1;
            rs8 += tanh_fast(c[mt][nt][2] + d0) * w0 + tanh_fast(c[mt][nt][3] + d1) * w1;
        }
        rs0 += __shfl_xor_sync(0xffffffffu, rs0, 1);
        rs0 += __shfl_xor_sync(0xffffffffu, rs0, 2);
        rs8 += __shfl_xor_sync(0xffffffffu, rs8, 1);
        rs8 += __shfl_xor_sync(0xffffffffu, rs8, 2);
        if (tig == 0) {
            int r0 = m0 + wm * 32 + mt * 16 + g;
            g_part[(size_t)r0 * 16 + blockIdx.x * 2 + wn] = rs0;
            g_part[(size_t)(r0 + 8) * 16 + blockIdx.x * 2 + wn] = rs8;
        }
    }
}

// ---------------- reduce 16 partials -> l[b][t] ----------------
__global__ void k_lred(const float* __restrict__ vd_b) {
    int r = blockIdx.x * 256 + threadIdx.x;
    const float4* p = (const float4*)(g_part + (size_t)r * 16);
    float tot = vd_b[0];
    #pragma unroll
    for (int i = 0; i < 4; i++) {
        float4 a = p[i];
        tot += a.x + a.y + a.z + a.w;
    }
    int tt = r >> 9;
    int b = r & 511;
    g_l[b * T_DIM + tt] = tot;
}

// ---------------- beta = softmax_t(l) -> out[512 + b*128 + t] ----------------
__global__ void k_beta(float* __restrict__ out) {
    __shared__ float red[128];
    int b = blockIdx.x;
    int tid = threadIdx.x;
    float v = g_l[b * T_DIM + tid];
    red[tid] = v;
    __syncthreads();
    for (int o = 64; o; o >>= 1) { if (tid < o) red[tid] = fmaxf(red[tid], red[tid + o]); __syncthreads(); }
    float mx = red[0];
    __syncthreads();
    float e = __expf(v - mx);
    red[tid] = e;
    __syncthreads();
    for (int o = 64; o; o >>= 1) { if (tid < o) red[tid] += red[tid + o]; __syncthreads(); }
    out[B_DIM + b * T_DIM + tid] = e / red[0];
}

// ---------------- ctx + logits fused ----------------
__global__ void k_out(float* __restrict__ out, const float* __restrict__ out_w,
                      const float* __restrict__ out_b) {
    __shared__ float s_beta[T_DIM];
    __shared__ float red[512];
    int b = blockIdx.x;
    int tid = threadIdx.x;
    if (tid < T_DIM) s_beta[tid] = out[B_DIM + b * T_DIM + tid];
    __syncthreads();
    float acc = 0.0f;
    #pragma unroll 4
    for (int tt = 0; tt < T_DIM; tt++)
        acc += s_beta[tt] * g_hseq[(size_t)tt * B_DIM * M_DIM + b * M_DIM + tid];
    red[tid] = acc * out_w[tid];
    __syncthreads();
    for (int o = 256; o; o >>= 1) { if (tid < o) red[tid] += red[tid + o]; __syncthreads(); }
    if (tid == 0) out[b] = red[0] + out_b[0];
}

// ---------------- host launcher ----------------
extern "C" void kernel_launch(void* const* d_in, const int* in_sizes, int n_in,
                              void* d_out, int out_size) {
    const float* x    = (const float*)d_in[0];
    const float* h0   = (const float*)d_in[1];
    const float* c0   = (const float*)d_in[2];
    const float* Wih  = (const float*)d_in[3];
    const float* Whh  = (const float*)d_in[4];
    const float* b_ih = (const float*)d_in[5];
    const float* b_hh = (const float*)d_in[6];
    const float* We_w = (const float*)d_in[7];
    const float* We_b = (const float*)d_in[8];
    const float* Ue_w = (const float*)d_in[9];
    const float* Ue_b = (const float*)d_in[10];
    const float* ve_w = (const float*)d_in[11];
    const float* ve_b = (const float*)d_in[12];
    const float* Ud_w = (const float*)d_in[13];
    const float* Ud_b = (const float*)d_in[14];
    const float* vd_w = (const float*)d_in[15];
    const float* vd_b = (const float*)d_in[16];
    const float* out_w = (const float*)d_in[17];
    const float* out_b = (const float*)d_in[18];
    float* out = (float*)d_out;

    k_init<<<B_DIM, M_DIM>>>(h0, c0);
    k_ue<<<dim3(B_DIM, N_DIM / 64), 256>>>(x, Ue_w, Ue_b);
    k_we<<<dim3(T_DIM / 64, B_DIM / 64, 8), 256>>>(We_w);
    for (int t = 0; t < T_DIM; t++) {
        k_e<<<B_DIM, 512>>>(t, x, We_b, ve_w, ve_b);
        k_gatescell<<<dim3(M_DIM / 16, B_DIM / 64), 256>>>(t, Wih, Whh, b_ih, b_hh, We_w);
    }
    k_ud<<<dim3(M_DIM / 64, (T_DIM * B_DIM) / 128), 256>>>(Ud_w, Ud_b, vd_w);
    k_lred<<<(T_DIM * B_DIM) / 256, 256>>>(vd_b);
    k_beta<<<B_DIM, T_DIM>>>(out);
    k_out<<<B_DIM, M_DIM>>>(out, out_w, out_b);
}

// round 15
// speedup vs baseline: 1.0344x; 1.0344x over previous
#include <cuda_runtime.h>
#include <cuda_bf16.h>
#include <cuda_fp16.h>
#include <cstdint>
#include <math.h>

#define T_DIM 128
#define B_DIM 512
#define N_DIM 256
#define M_DIM 512
#define G_DIM 2048   // 4*M
#define K_GATES 768  // N + M
#define SPAD 36      // smem row stride for tf32 kernels
#define HCPAD 36     // stride for epilogue hc/We tiles (float4-aligned)

// ---------------- device scratch (no allocation allowed) ----------------
__device__ __half g_UeX[B_DIM * T_DIM * N_DIM];     // [b][s][n]  33.5 MB (fp16)
__device__ float g_hbuf[2][B_DIM * M_DIM];          // double-buffered h
__device__ float g_cbuf[2][B_DIM * M_DIM];          // double-buffered c
__device__ float g_hseq[T_DIM * B_DIM * M_DIM];     // 134 MB
__device__ float g_xt[B_DIM * N_DIM];               // x_tilde
__device__ float g_wepart[32 * B_DIM * T_DIM];      // split-K partials for we (8 MB)
__device__ float g_ghp[32 * B_DIM * 64];            // h@Whh^T partial, permuted (4 MB)
__device__ float g_part[(T_DIM * B_DIM) * 16];      // per-(colblock,warp) row sums
__device__ float g_l[B_DIM * T_DIM];                // attention logits l

// ---------------- fast math helpers ----------------
__device__ __forceinline__ float tanh_fast(float x) {
    float y;
    asm("tanh.approx.f32 %0, %1;" : "=f"(y) : "f"(x));
    return y;
}
__device__ __forceinline__ float sigmoid_fast(float x) {
    return 0.5f * tanh_fast(0.5f * x) + 0.5f;
}

// ---------------- tf32 mma helpers ----------------
__device__ __forceinline__ void tf32_split(float v, uint32_t& hi, uint32_t& lo) {
    asm("cvt.rna.tf32.f32 %0, %1;" : "=r"(hi) : "f"(v));
    float r = v - __uint_as_float(hi);
    asm("cvt.rna.tf32.f32 %0, %1;" : "=r"(lo) : "f"(r));
}
__device__ __forceinline__ uint32_t tf32_hi(float v) {
    uint32_t hi;
    asm("cvt.rna.tf32.f32 %0, %1;" : "=r"(hi) : "f"(v));
    return hi;
}
__device__ __forceinline__ void mma_tf32(float* c, const uint32_t* a, const uint32_t* b) {
    asm volatile(
        "mma.sync.aligned.m16n8k8.row.col.f32.tf32.tf32.f32 "
        "{%0,%1,%2,%3}, {%4,%5,%6,%7}, {%8,%9}, {%0,%1,%2,%3};\n"
        : "+f"(c[0]), "+f"(c[1]), "+f"(c[2]), "+f"(c[3])
        : "r"(a[0]), "r"(a[1]), "r"(a[2]), "r"(a[3]), "r"(b[0]), "r"(b[1]));
}

// ---------------- init h,c into buffer 0 ----------------
__global__ void k_init(const float* __restrict__ h0, const float* __restrict__ c0) {
    int idx = blockIdx.x * blockDim.x + threadIdx.x;
    g_hbuf[0][idx] = h0[idx];
    g_cbuf[0][idx] = c0[idx];
}

// ---------------- Ue_x[b][s][n] (fp16 out) ----------------
__global__ void k_ue(const float* __restrict__ x, const float* __restrict__ Ue_w,
                     const float* __restrict__ Ue_b) {
    __shared__ float xs[T_DIM][64];
    int b = blockIdx.x;
    int n0 = blockIdx.y * 64;
    int tid = threadIdx.x;
    for (int idx = tid; idx < T_DIM * 64; idx += 256) {
        int t = idx >> 6, n = idx & 63;
        xs[t][n] = x[(size_t)t * B_DIM * N_DIM + b * N_DIM + n0 + n];
    }
    __syncthreads();
    for (int r = 0; r < 32; r++) {
        int o = tid + 256 * r;
        int s = o >> 6, n = o & 63;
        float acc = Ue_b[s];
        const float* uw = Ue_w + s * T_DIM;
        #pragma unroll 8
        for (int t = 0; t < T_DIM; t++) acc += xs[t][n] * uw[t];
        g_UeX[(b * T_DIM + s) * N_DIM + n0 + n] = __float2half_rn(acc);
    }
}

// ---------------- k_we (PROLOGUE ONLY, t=0): 8-slice split-K for we from h0,c0 ----
__global__ void __launch_bounds__(256) k_we(const float* __restrict__ We_w) {
    __shared__ float As[16][68];
    __shared__ float Bs[16][68];
    int cb = blockIdx.x, rb = blockIdx.y, kc = blockIdx.z;
    int tid = threadIdx.x;
    int tx = tid & 15, ty = tid >> 4;
    int kl = tid & 15, il = tid >> 4;
    int row0 = rb * 64, col0 = cb * 64;
    const float* src = (kc < 4) ? (g_hbuf[0] + kc * 128) : (g_cbuf[0] + (kc - 4) * 128);
    const float* wsrc = We_w + kc * 128;
    float acc[4][4] = {};
    for (int k0 = 0; k0 < 128; k0 += 16) {
        int k = k0 + kl;
        #pragma unroll
        for (int s = 0; s < 4; s++) {
            int i = il + s * 16;
            As[kl][i] = src[(size_t)(row0 + i) * M_DIM + k];
            Bs[kl][i] = wsrc[(size_t)(col0 + i) * 1024 + k];
        }
        __syncthreads();
        #pragma unroll
        for (int kk = 0; kk < 16; kk++) {
            float4 a4 = *(const float4*)&As[kk][ty * 4];
            float4 b4 = *(const float4*)&Bs[kk][tx * 4];
            float av[4] = {a4.x, a4.y, a4.z, a4.w};
            float bv[4] = {b4.x, b4.y, b4.z, b4.w};
            #pragma unroll
            for (int ii = 0; ii < 4; ii++)
                #pragma unroll
                for (int jj = 0; jj < 4; jj++) acc[ii][jj] += av[ii] * bv[jj];
        }
        __syncthreads();
    }
    #pragma unroll
    for (int ii = 0; ii < 4; ii++) {
        int row = row0 + ty * 4 + ii;
        #pragma unroll
        for (int jj = 0; jj < 4; jj++) {
            int s = col0 + tx * 4 + jj;
            g_wepart[(kc * B_DIM + row) * T_DIM + s] = acc[ii][jj];
        }
    }
}

// ---------------- k_e: 512 threads, s split 4-way, half2 loads -----------------
__global__ void __launch_bounds__(512) k_e(int t, const float* __restrict__ x,
                    const float* __restrict__ We_b,
                    const float* __restrict__ ve_w, const float* __restrict__ ve_b) {
    __shared__ float s_we[T_DIM];
    __shared__ float s_ve[T_DIM];
    __shared__ float s_part[4 * N_DIM];
    __shared__ float red[256];
    int b = blockIdx.x;
    int tid = threadIdx.x;
    int ns = (t == 0) ? 8 : 32;
    if (tid < T_DIM) {
        float w = We_b[tid];
        for (int kc = 0; kc < ns; kc++)
            w += g_wepart[(kc * B_DIM + b) * T_DIM + tid];
        s_we[tid] = w;
        s_ve[tid] = ve_w[tid];
    }
    __syncthreads();

    int np = tid & 127;
    int sq = tid >> 7;
    const __half2* ue = (const __half2*)(g_UeX + ((size_t)b * T_DIM + sq * 32) * N_DIM) + np;
    float acc0 = 0.0f, acc1 = 0.0f;
    #pragma unroll
    for (int s0 = 0; s0 < 32; s0 += 8) {
        __half2 v[8];
        #pragma unroll
        for (int u = 0; u < 8; u++) v[u] = __ldg(ue + (size_t)(s0 + u) * (N_DIM / 2));
        #pragma unroll
        for (int u = 0; u < 8; u++) {
            int s = sq * 32 + s0 + u;
            float2 f = __half22float2(v[u]);
            float wes = s_we[s], ves = s_ve[s];
            acc0 += tanh_fast(wes + f.x) * ves;
            acc1 += tanh_fast(wes + f.y) * ves;
        }
    }
    *(float2*)&s_part[sq * N_DIM + 2 * np] = make_float2(acc0, acc1);
    __syncthreads();

    float e = 0.0f;
    if (tid < N_DIM) {
        e = ve_b[0];
        #pragma unroll
        for (int q = 0; q < 4; q++) e += s_part[q * N_DIM + tid];
        red[tid] = e;
    }
    __syncthreads();
    for (int o = 128; o >= 32; o >>= 1) {
        if (tid < o) red[tid] = fmaxf(red[tid], red[tid + o]);
        __syncthreads();
    }
    if (tid < 32) {
        float v = red[tid];
        #pragma unroll
        for (int o = 16; o; o >>= 1) v = fmaxf(v, __shfl_xor_sync(0xffffffffu, v, o));
        red[tid] = v;
    }
    __syncthreads();
    float mx = red[0];
    float ev = 0.0f;
    __syncthreads();
    if (tid < N_DIM) {
        ev = __expf(e - mx);
        red[tid] = ev;
    }
    __syncthreads();
    for (int o = 128; o >= 32; o >>= 1) {
        if (tid < o) red[tid] += red[tid + o];
        __syncthreads();
    }
    if (tid < 32) {
        float v = red[tid];
        #pragma unroll
        for (int o = 16; o; o >>= 1) v += __shfl_xor_sync(0xffffffffu, v, o);
        red[tid] = v;
    }
    __syncthreads();
    if (tid < N_DIM) {
        float alpha = ev / red[0];
        g_xt[b * N_DIM + tid] = alpha * x[(size_t)t * B_DIM * N_DIM + b * N_DIM + tid];
    }
}

// ---------------- k_gh: gh = h(t-1) @ Whh^T (permuted cols), K=512 ---------------
// grid (32, 4): block 128 rows x 64 permuted gate cols. Runs CONCURRENT with k_e.
__global__ void __launch_bounds__(256) k_gh(int t, const float* __restrict__ Whh) {
    __shared__ float As[128 * SPAD];
    __shared__ float Bs[64 * SPAD];
    int in = t & 1;
    const float* hin = g_hbuf[in];
    int tid = threadIdx.x;
    int w = tid >> 5, lane = tid & 31;
    int g = lane >> 2, tig = lane & 3;
    int wm = w & 3, wn = w >> 2;
    int cb = blockIdx.x;
    int m0 = blockIdx.y * 128;
    int r = tid >> 3, kq = (tid & 7) * 4;
    float c[2][4][4] = {};

    for (int k0 = 0; k0 < M_DIM; k0 += 32) {
        #pragma unroll
        for (int i = 0; i < 4; i++) {
            int row = r + 32 * i;
            *(float4*)&As[row * SPAD + kq] =
                *(const float4*)(hin + (size_t)(m0 + row) * M_DIM + k0 + kq);
        }
        #pragma unroll
        for (int i2 = 0; i2 < 2; i2++) {
            int i = r + 32 * i2;
            int j = (i & 3) * M_DIM + cb * 16 + (i >> 2);
            *(float4*)&Bs[i * SPAD + kq] =
                *(const float4*)(Whh + (size_t)j * M_DIM + k0 + kq);
        }
        __syncthreads();
        #pragma unroll
        for (int kt = 0; kt < 4; kt++) {
            int kk = kt * 8 + tig;
            uint32_t ahi[2][4], alo[2][4], bhi[4][2], blo[4][2];
            #pragma unroll
            for (int mt = 0; mt < 2; mt++) {
                int rb = wm * 32 + mt * 16 + g;
                tf32_split(As[rb * SPAD + kk],           ahi[mt][0], alo[mt][0]);
                tf32_split(As[(rb + 8) * SPAD + kk],     ahi[mt][1], alo[mt][1]);
                tf32_split(As[rb * SPAD + kk + 4],       ahi[mt][2], alo[mt][2]);
                tf32_split(As[(rb + 8) * SPAD + kk + 4], ahi[mt][3], alo[mt][3]);
            }
            #pragma unroll
            for (int nt = 0; nt < 4; nt++) {
                int nb = wn * 32 + nt * 8 + g;
                tf32_split(Bs[nb * SPAD + kk],     bhi[nt][0], blo[nt][0]);
                tf32_split(Bs[nb * SPAD + kk + 4], bhi[nt][1], blo[nt][1]);
            }
            #pragma unroll
            for (int mt = 0; mt < 2; mt++)
                #pragma unroll
                for (int nt = 0; nt < 4; nt++) {
                    mma_tf32(c[mt][nt], ahi[mt], bhi[nt]);
                    mma_tf32(c[mt][nt], ahi[mt], blo[nt]);
                    mma_tf32(c[mt][nt], alo[mt], bhi[nt]);
                }
        }
        __syncthreads();
    }
    #pragma unroll
    for (int mt = 0; mt < 2; mt++) {
        int rl = wm * 32 + mt * 16 + g;
        #pragma unroll
        for (int nt = 0; nt < 4; nt++) {
            int qd = wn * 32 + nt * 8 + tig * 2;
            size_t base0 = (size_t)(cb * B_DIM + m0 + rl) * 64 + qd;
            size_t base8 = (size_t)(cb * B_DIM + m0 + rl + 8) * 64 + qd;
            g_ghp[base0]     = c[mt][nt][0];
            g_ghp[base0 + 1] = c[mt][nt][1];
            g_ghp[base8]     = c[mt][nt][2];
            g_ghp[base8 + 1] = c[mt][nt][3];
        }
    }
}

// ---------------- k_gx: xt @ Wih^T (K=256) + ghp + cell + we-partial -------------
__global__ void __launch_bounds__(256) k_gx(int t,
        const float* __restrict__ Wih,
        const float* __restrict__ b_ih, const float* __restrict__ b_hh,
        const float* __restrict__ We_w) {
    __shared__ float pool[128 * 72];
    float* As = pool;
    float* Bs = pool + 128 * SPAD;
    int in = t & 1, ob = in ^ 1;
    const float* cin = g_cbuf[in];
    float* hout = g_hbuf[ob];
    float* cout = g_cbuf[ob];
    int tid = threadIdx.x;
    int w = tid >> 5, lane = tid & 31;
    int g = lane >> 2, tig = lane & 3;
    int wm = w & 3, wn = w >> 2;
    int cb = blockIdx.x;
    int m0 = blockIdx.y * 128;
    int r = tid >> 3, kq = (tid & 7) * 4;
    float c[2][4][4] = {};

    for (int k0 = 0; k0 < N_DIM; k0 += 32) {
        #pragma unroll
        for (int i = 0; i < 4; i++) {
            int row = r + 32 * i;
            *(float4*)&As[row * SPAD + kq] =
                *(const float4*)(g_xt + (size_t)(m0 + row) * N_DIM + k0 + kq);
        }
        #pragma unroll
        for (int i2 = 0; i2 < 2; i2++) {
            int i = r + 32 * i2;
            int j = (i & 3) * M_DIM + cb * 16 + (i >> 2);
            *(float4*)&Bs[i * SPAD + kq] =
                *(const float4*)(Wih + (size_t)j * N_DIM + k0 + kq);
        }
        __syncthreads();
        #pragma unroll
        for (int kt = 0; kt < 4; kt++) {
            int kk = kt * 8 + tig;
            uint32_t ahi[2][4], alo[2][4], bhi[4][2], blo[4][2];
            #pragma unroll
            for (int mt = 0; mt < 2; mt++) {
                int rb = wm * 32 + mt * 16 + g;
                tf32_split(As[rb * SPAD + kk],           ahi[mt][0], alo[mt][0]);
                tf32_split(As[(rb + 8) * SPAD + kk],     ahi[mt][1], alo[mt][1]);
                tf32_split(As[rb * SPAD + kk + 4],       ahi[mt][2], alo[mt][2]);
                tf32_split(As[(rb + 8) * SPAD + kk + 4], ahi[mt][3], alo[mt][3]);
            }
            #pragma unroll
            for (int nt = 0; nt < 4; nt++) {
                int nb = wn * 32 + nt * 8 + g;
                tf32_split(Bs[nb * SPAD + kk],     bhi[nt][0], blo[nt][0]);
                tf32_split(Bs[nb * SPAD + kk + 4], bhi[nt][1], blo[nt][1]);
            }
            #pragma unroll
            for (int mt = 0; mt < 2; mt++)
                #pragma unroll
                for (int nt = 0; nt < 4; nt++) {
                    mma_tf32(c[mt][nt], ahi[mt], bhi[nt]);
                    mma_tf32(c[mt][nt], ahi[mt], blo[nt]);
                    mma_tf32(c[mt][nt], alo[mt], bhi[nt]);
                }
        }
        __syncthreads();
    }

    // stage accumulators: pool[row][68]
    #pragma unroll
    for (int mt = 0; mt < 2; mt++) {
        int rl = wm * 32 + mt * 16 + g;
        #pragma unroll
        for (int nt = 0; nt < 4; nt++) {
            int qd = wn * 32 + nt * 8 + tig * 2;
            pool[rl * 68 + qd]           = c[mt][nt][0];
            pool[rl * 68 + qd + 1]       = c[mt][nt][1];
            pool[(rl + 8) * 68 + qd]     = c[mt][nt][2];
            pool[(rl + 8) * 68 + qd + 1] = c[mt][nt][3];
        }
    }
    __syncthreads();

    // cell (adds h-partial from g_ghp)
    float hnv[8], cnv[8];
    #pragma unroll
    for (int u = 0; u < 8; u++) {
        int idx = tid + 256 * u;
        int rl = idx >> 4, ml = idx & 15;
        int b = m0 + rl;
        int m = cb * 16 + ml;
        float4 gh4 = *(const float4*)&g_ghp[(size_t)(cb * B_DIM + b) * 64 + ml * 4];
        float gi = pool[rl * 68 + ml * 4 + 0] + gh4.x + b_ih[m]             + b_hh[m];
        float gf = pool[rl * 68 + ml * 4 + 1] + gh4.y + b_ih[M_DIM + m]     + b_hh[M_DIM + m];
        float gg = pool[rl * 68 + ml * 4 + 2] + gh4.z + b_ih[2 * M_DIM + m] + b_hh[2 * M_DIM + m];
        float go = pool[rl * 68 + ml * 4 + 3] + gh4.w + b_ih[3 * M_DIM + m] + b_hh[3 * M_DIM + m];
        float cprev = cin[(size_t)b * M_DIM + m];
        float si = sigmoid_fast(gi);
        float sf = sigmoid_fast(gf);
        float tg = tanh_fast(gg);
        float so = sigmoid_fast(go);
        float cn = sf * cprev + si * tg;
        float hn = so * tanh_fast(cn);
        cout[(size_t)b * M_DIM + m] = cn;
        hout[(size_t)b * M_DIM + m] = hn;
        g_hseq[(size_t)t * B_DIM * M_DIM + (size_t)b * M_DIM + m] = hn;
        hnv[u] = hn;
        cnv[u] = cn;
    }
    __syncthreads();

    if (t == T_DIM - 1) return;

    // we-partial epilogue
    float* s_hc = pool;
    float* s_We = pool + 128 * HCPAD;
    #pragma unroll
    for (int u = 0; u < 8; u++) {
        int idx = tid + 256 * u;
        int rl = idx >> 4, ml = idx & 15;
        s_hc[rl * HCPAD + ml]      = hnv[u];
        s_hc[rl * HCPAD + 16 + ml] = cnv[u];
    }
    for (int i = tid; i < 128 * 16; i += 256) {
        int s = i >> 4, kh = i & 15;
        s_We[s * HCPAD + kh]      = We_w[(size_t)s * 1024 + cb * 16 + kh];
        s_We[s * HCPAD + 16 + kh] = We_w[(size_t)s * 1024 + 512 + cb * 16 + kh];
    }
    __syncthreads();

    int tx = tid & 15, ty4 = tid >> 4;
    #pragma unroll
    for (int sub = 0; sub < 4; sub++) {
        int r0 = (sub & 1) * 64, s0 = (sub >> 1) * 64;
        float acc[4][4] = {};
        #pragma unroll
        for (int kk = 0; kk < 32; kk += 4) {
            float4 a4[4], b4[4];
            #pragma unroll
            for (int ii = 0; ii < 4; ii++)
                a4[ii] = *(const float4*)&s_hc[(r0 + ty4 * 4 + ii) * HCPAD + kk];
            #pragma unroll
            for (int jj = 0; jj < 4; jj++)
                b4[jj] = *(const float4*)&s_We[(s0 + tx * 4 + jj) * HCPAD + kk];
            #pragma unroll
            for (int ii = 0; ii < 4; ii++) {
                float av[4] = {a4[ii].x, a4[ii].y, a4[ii].z, a4[ii].w};
                #pragma unroll
                for (int jj = 0; jj < 4; jj++) {
                    acc[ii][jj] += av[0] * b4[jj].x + av[1] * b4[jj].y
                                 + av[2] * b4[jj].z + av[3] * b4[jj].w;
                }
            }
        }
        #pragma unroll
        for (int ii = 0; ii < 4; ii++) {
            int row = m0 + r0 + ty4 * 4 + ii;
            #pragma unroll
            for (int jj = 0; jj < 4; jj++)
                g_wepart[(cb * B_DIM + row) * T_DIM + s0 + tx * 4 + jj] = acc[ii][jj];
        }
    }
}

// ---------------- k_ud (tf32 2-term mma) ----------------
__global__ void __launch_bounds__(256) k_ud(
        const float* __restrict__ Ud_w, const float* __restrict__ Ud_b,
        const float* __restrict__ vd_w) {
    __shared__ float As[128 * SPAD];
    __shared__ float Bs[64 * SPAD];
    int tid = threadIdx.x;
    int w = tid >> 5, lane = tid & 31;
    int g = lane >> 2, tig = lane & 3;
    int wm = w & 3, wn = w >> 2;
    int m0 = blockIdx.y * 128, n0 = blockIdx.x * 64;
    int r = tid >> 3, kq = (tid & 7) * 4;
    float c[2][4][4] = {};

    for (int k0 = 0; k0 < M_DIM; k0 += 32) {
        #pragma unroll
        for (int i = 0; i < 4; i++) {
            int row = r + 32 * i;
            *(float4*)&As[row * SPAD + kq] =
                *(const float4*)(g_hseq + (size_t)(m0 + row) * M_DIM + k0 + kq);
        }
        #pragma unroll
        for (int i = 0; i < 2; i++) {
            int row = r + 32 * i;
            *(float4*)&Bs[row * SPAD + kq] =
                *(const float4*)(Ud_w + (size_t)(n0 + row) * M_DIM + k0 + kq);
        }
        __syncthreads();
        #pragma unroll
        for (int kt = 0; kt < 4; kt++) {
            int kk = kt * 8 + tig;
            uint32_t ahi[2][4], alo[2][4], bhi[4][2];
            #pragma unroll
            for (int mt = 0; mt < 2; mt++) {
                int rb = wm * 32 + mt * 16 + g;
                tf32_split(As[rb * SPAD + kk],           ahi[mt][0], alo[mt][0]);
                tf32_split(As[(rb + 8) * SPAD + kk],     ahi[mt][1], alo[mt][1]);
                tf32_split(As[rb * SPAD + kk + 4],       ahi[mt][2], alo[mt][2]);
                tf32_split(As[(rb + 8) * SPAD + kk + 4], ahi[mt][3], alo[mt][3]);
            }
            #pragma unroll
            for (int nt = 0; nt < 4; nt++) {
                int nb = wn * 32 + nt * 8 + g;
                bhi[nt][0] = tf32_hi(Bs[nb * SPAD + kk]);
                bhi[nt][1] = tf32_hi(Bs[nb * SPAD + kk + 4]);
            }
            #pragma unroll
            for (int mt = 0; mt < 2; mt++)
                #pragma unroll
                for (int nt = 0; nt < 4; nt++) {
                    mma_tf32(c[mt][nt], ahi[mt], bhi[nt]);
                    mma_tf32(c[mt][nt], alo[mt], bhi[nt]);
                }
        }
        __syncthreads();
    }
    #pragma unroll
    for (int mt = 0; mt < 2; mt++) {
        float rs0 = 0.0f, rs8 = 0.0f;
        #pragma unroll
        for (int nt = 0; nt < 4; nt++) {
            int j0 = n0 + wn * 32 + nt * 8 + tig * 2;
            float w0 = vd_w[j0], w1 = vd_w[j0 + 1];
            float d0 = Ud_b[j0], d1 = Ud_b[j0 + 1];
            rs0 += tanh_fast(c[mt][nt][0] + d0) * w0 + tanh_fast(c[mt][nt][1] + d1) * w1;
            rs8 += tanh_fast(c[mt][nt][2] + d0) * w0 + tanh_fast(c[mt][nt][3] + d1) * w1;
        }
        rs0 += __shfl_xor_sync(0xffffffffu, rs0, 1);
        rs0 += __shfl_xor_sync(0xffffffffu, rs0, 2);
        rs8 += __shfl_xor_sync(0xffffffffu, rs8, 1);
        rs8 += __shfl_xor_sync(0xffffffffu, rs8, 2);
        if (tig == 0) {
            int r0 = m0 + wm * 32 + mt * 16 + g;
            g_part[(size_t)r0 * 16 + blockIdx.x * 2 + wn] = rs0;
            g_part[(size_t)(r0 + 8) * 16 + blockIdx.x * 2 + wn] = rs8;
        }
    }
}

// ---------------- reduce 16 partials -> l[b][t] ----------------
__global__ void k_lred(const float* __restrict__ vd_b) {
    int r = blockIdx.x * 256 + threadIdx.x;
    const float4* p = (const float4*)(g_part + (size_t)r * 16);
    float tot = vd_b[0];
    #pragma unroll
    for (int i = 0; i < 4; i++) {
        float4 a = p[i];
        tot += a.x + a.y + a.z + a.w;
    }
    int tt = r >> 9;
    int b = r & 511;
    g_l[b * T_DIM + tt] = tot;
}

// ---------------- beta = softmax_t(l) -> out[512 + b*128 + t] ----------------
__global__ void k_beta(float* __restrict__ out) {
    __shared__ float red[128];
    int b = blockIdx.x;
    int tid = threadIdx.x;
    float v = g_l[b * T_DIM + tid];
    red[tid] = v;
    __syncthreads();
    for (int o = 64; o; o >>= 1) { if (tid < o) red[tid] = fmaxf(red[tid], red[tid + o]); __syncthreads(); }
    float mx = red[0];
    __syncthreads();
    float e = __expf(v - mx);
    red[tid] = e;
    __syncthreads();
    for (int o = 64; o; o >>= 1) { if (tid < o) red[tid] += red[tid + o]; __syncthreads(); }
    out[B_DIM + b * T_DIM + tid] = e / red[0];
}

// ---------------- ctx + logits fused ----------------
__global__ void k_out(float* __restrict__ out, const float* __restrict__ out_w,
                      const float* __restrict__ out_b) {
    __shared__ float s_beta[T_DIM];
    __shared__ float red[512];
    int b = blockIdx.x;
    int tid = threadIdx.x;
    if (tid < T_DIM) s_beta[tid] = out[B_DIM + b * T_DIM + tid];
    __syncthreads();
    float acc = 0.0f;
    #pragma unroll 4
    for (int tt = 0; tt < T_DIM; tt++)
        acc += s_beta[tt] * g_hseq[(size_t)tt * B_DIM * M_DIM + b * M_DIM + tid];
    red[tid] = acc * out_w[tid];
    __syncthreads();
    for (int o = 256; o; o >>= 1) { if (tid < o) red[tid] += red[tid + o]; __syncthreads(); }
    if (tid == 0) out[b] = red[0] + out_b[0];
}

// ---------------- host launcher (2-stream overlap, graph-capturable) ----------------
extern "C" void kernel_launch(void* const* d_in, const int* in_sizes, int n_in,
                              void* d_out, int out_size) {
    const float* x    = (const float*)d_in[0];
    const float* h0   = (const float*)d_in[1];
    const float* c0   = (const float*)d_in[2];
    const float* Wih  = (const float*)d_in[3];
    const float* Whh  = (const float*)d_in[4];
    const float* b_ih = (const float*)d_in[5];
    const float* b_hh = (const float*)d_in[6];
    const float* We_w = (const float*)d_in[7];
    const float* We_b = (const float*)d_in[8];
    const float* Ue_w = (const float*)d_in[9];
    const float* Ue_b = (const float*)d_in[10];
    const float* ve_w = (const float*)d_in[11];
    const float* ve_b = (const float*)d_in[12];
    const float* Ud_w = (const float*)d_in[13];
    const float* Ud_b = (const float*)d_in[14];
    const float* vd_w = (const float*)d_in[15];
    const float* vd_b = (const float*)d_in[16];
    const float* out_w = (const float*)d_in[17];
    const float* out_b = (const float*)d_in[18];
    float* out = (float*)d_out;

    static cudaStream_t sB = nullptr;
    static cudaEvent_t evFork = nullptr, evGh = nullptr, evX = nullptr;
    if (sB == nullptr) {
        cudaStreamCreateWithFlags(&sB, cudaStreamNonBlocking);
        cudaEventCreateWithFlags(&evFork, cudaEventDisableTiming);
        cudaEventCreateWithFlags(&evGh, cudaEventDisableTiming);
        cudaEventCreateWithFlags(&evX, cudaEventDisableTiming);
    }
    cudaStream_t s0 = 0;   // same default stream the <<<>>> launches use

    k_init<<<B_DIM, M_DIM>>>(h0, c0);
    k_ue<<<dim3(B_DIM, N_DIM / 64), 256>>>(x, Ue_w, Ue_b);
    k_we<<<dim3(T_DIM / 64, B_DIM / 64, 8), 256>>>(We_w);

    cudaEventRecord(evFork, s0);
    cudaStreamWaitEvent(sB, evFork, 0);

    for (int t = 0; t < T_DIM; t++) {
        k_e<<<B_DIM, 512, 0, s0>>>(t, x, We_b, ve_w, ve_b);
        k_gh<<<dim3(M_DIM / 16, B_DIM / 128), 256, 0, sB>>>(t, Whh);
        cudaEventRecord(evGh, sB);
        cudaStreamWaitEvent(s0, evGh, 0);
        k_gx<<<dim3(M_DIM / 16, B_DIM / 128), 256, 0, s0>>>(t, Wih, b_ih, b_hh, We_w);
        if (t < T_DIM - 1) {
            cudaEventRecord(evX, s0);
            cudaStreamWaitEvent(sB, evX, 0);
        }
    }

    k_ud<<<dim3(M_DIM / 64, (T_DIM * B_DIM) / 128), 256>>>(Ud_w, Ud_b, vd_w);
    k_lred<<<(T_DIM * B_DIM) / 256, 256>>>(vd_b);
    k_beta<<<B_DIM, T_DIM>>>(out);
    k_out<<<B_DIM, M_DIM>>>(out, out_w, out_b);
}

// round 16
// speedup vs baseline: 1.4672x; 1.4183x over previous
#include <cuda_runtime.h>
#include <cuda_bf16.h>
#include <cuda_fp16.h>
#include <cstdint>
#include <math.h>

#define T_DIM 128
#define B_DIM 512
#define N_DIM 256
#define M_DIM 512
#define G_DIM 2048   // 4*M
#define K_GATES 768  // N + M
#define NCHUNK 24
#define SPAD 36      // smem row stride for tf32 kernels
#define HCPAD 36     // stride for epilogue hc/We tiles (float4-aligned)

// ---------------- device scratch (no allocation allowed) ----------------
__device__ __half g_UeX[B_DIM * T_DIM * N_DIM];     // [b][s][n]  33.5 MB (fp16)
__device__ float g_hbuf[2][B_DIM * M_DIM];          // double-buffered h
__device__ float g_cbuf[2][B_DIM * M_DIM];          // double-buffered c
__device__ float g_hseq[T_DIM * B_DIM * M_DIM];     // 134 MB
__device__ float g_xt[B_DIM * N_DIM];               // x_tilde
__device__ float g_wepart[32 * B_DIM * T_DIM];      // split-K partials for we (8 MB)
__device__ float g_part[(T_DIM * B_DIM) * 16];      // per-(colblock,warp) row sums
__device__ float g_l[B_DIM * T_DIM];                // attention logits l

// ---------------- fast math helpers ----------------
__device__ __forceinline__ float tanh_fast(float x) {
    float y;
    asm("tanh.approx.f32 %0, %1;" : "=f"(y) : "f"(x));
    return y;
}
__device__ __forceinline__ float sigmoid_fast(float x) {
    return 0.5f * tanh_fast(0.5f * x) + 0.5f;
}

// ---------------- tf32 mma helpers ----------------
__device__ __forceinline__ void tf32_split(float v, uint32_t& hi, uint32_t& lo) {
    asm("cvt.rna.tf32.f32 %0, %1;" : "=r"(hi) : "f"(v));
    float r = v - __uint_as_float(hi);
    asm("cvt.rna.tf32.f32 %0, %1;" : "=r"(lo) : "f"(r));
}
__device__ __forceinline__ uint32_t tf32_hi(float v) {
    uint32_t hi;
    asm("cvt.rna.tf32.f32 %0, %1;" : "=r"(hi) : "f"(v));
    return hi;
}
__device__ __forceinline__ void mma_tf32(float* c, const uint32_t* a, const uint32_t* b) {
    asm volatile(
        "mma.sync.aligned.m16n8k8.row.col.f32.tf32.tf32.f32 "
        "{%0,%1,%2,%3}, {%4,%5,%6,%7}, {%8,%9}, {%0,%1,%2,%3};\n"
        : "+f"(c[0]), "+f"(c[1]), "+f"(c[2]), "+f"(c[3])
        : "r"(a[0]), "r"(a[1]), "r"(a[2]), "r"(a[3]), "r"(b[0]), "r"(b[1]));
}

// ---------------- init h,c into buffer 0 ----------------
__global__ void k_init(const float* __restrict__ h0, const float* __restrict__ c0) {
    int idx = blockIdx.x * blockDim.x + threadIdx.x;
    g_hbuf[0][idx] = h0[idx];
    g_cbuf[0][idx] = c0[idx];
}

// ---------------- Ue_x[b][s][n] (fp16 out) ----------------
__global__ void k_ue(const float* __restrict__ x, const float* __restrict__ Ue_w,
                     const float* __restrict__ Ue_b) {
    __shared__ float xs[T_DIM][64];
    int b = blockIdx.x;
    int n0 = blockIdx.y * 64;
    int tid = threadIdx.x;
    for (int idx = tid; idx < T_DIM * 64; idx += 256) {
        int t = idx >> 6, n = idx & 63;
        xs[t][n] = x[(size_t)t * B_DIM * N_DIM + b * N_DIM + n0 + n];
    }
    __syncthreads();
    for (int r = 0; r < 32; r++) {
        int o = tid + 256 * r;
        int s = o >> 6, n = o & 63;
        float acc = Ue_b[s];
        const float* uw = Ue_w + s * T_DIM;
        #pragma unroll 8
        for (int t = 0; t < T_DIM; t++) acc += xs[t][n] * uw[t];
        g_UeX[(b * T_DIM + s) * N_DIM + n0 + n] = __float2half_rn(acc);
    }
}

// ---------------- k_we (PROLOGUE ONLY, t=0): 8-slice split-K for we from h0,c0 ----
__global__ void __launch_bounds__(256) k_we(const float* __restrict__ We_w) {
    __shared__ float As[16][68];
    __shared__ float Bs[16][68];
    int cb = blockIdx.x, rb = blockIdx.y, kc = blockIdx.z;
    int tid = threadIdx.x;
    int tx = tid & 15, ty = tid >> 4;
    int kl = tid & 15, il = tid >> 4;
    int row0 = rb * 64, col0 = cb * 64;
    const float* src = (kc < 4) ? (g_hbuf[0] + kc * 128) : (g_cbuf[0] + (kc - 4) * 128);
    const float* wsrc = We_w + kc * 128;
    float acc[4][4] = {};
    for (int k0 = 0; k0 < 128; k0 += 16) {
        int k = k0 + kl;
        #pragma unroll
        for (int s = 0; s < 4; s++) {
            int i = il + s * 16;
            As[kl][i] = src[(size_t)(row0 + i) * M_DIM + k];
            Bs[kl][i] = wsrc[(size_t)(col0 + i) * 1024 + k];
        }
        __syncthreads();
        #pragma unroll
        for (int kk = 0; kk < 16; kk++) {
            float4 a4 = *(const float4*)&As[kk][ty * 4];
            float4 b4 = *(const float4*)&Bs[kk][tx * 4];
            float av[4] = {a4.x, a4.y, a4.z, a4.w};
            float bv[4] = {b4.x, b4.y, b4.z, b4.w};
            #pragma unroll
            for (int ii = 0; ii < 4; ii++)
                #pragma unroll
                for (int jj = 0; jj < 4; jj++) acc[ii][jj] += av[ii] * bv[jj];
        }
        __syncthreads();
    }
    #pragma unroll
    for (int ii = 0; ii < 4; ii++) {
        int row = row0 + ty * 4 + ii;
        #pragma unroll
        for (int jj = 0; jj < 4; jj++) {
            int s = col0 + tx * 4 + jj;
            g_wepart[(kc * B_DIM + row) * T_DIM + s] = acc[ii][jj];
        }
    }
}

// ---------------- k_e: 512 threads, s split 4-way, half2 loads -----------------
__global__ void __launch_bounds__(512) k_e(int t, const float* __restrict__ x,
                    const float* __restrict__ We_b,
                    const float* __restrict__ ve_w, const float* __restrict__ ve_b) {
    __shared__ float s_we[T_DIM];
    __shared__ float s_ve[T_DIM];
    __shared__ float s_part[4 * N_DIM];
    __shared__ float red[256];
    int b = blockIdx.x;
    int tid = threadIdx.x;
    int ns = (t == 0) ? 8 : 32;
    if (tid < T_DIM) {
        float w = We_b[tid];
        for (int kc = 0; kc < ns; kc++)
            w += g_wepart[(kc * B_DIM + b) * T_DIM + tid];
        s_we[tid] = w;
        s_ve[tid] = ve_w[tid];
    }
    __syncthreads();

    int np = tid & 127;
    int sq = tid >> 7;
    const __half2* ue = (const __half2*)(g_UeX + ((size_t)b * T_DIM + sq * 32) * N_DIM) + np;
    float acc0 = 0.0f, acc1 = 0.0f;
    #pragma unroll
    for (int s0 = 0; s0 < 32; s0 += 8) {
        __half2 v[8];
        #pragma unroll
        for (int u = 0; u < 8; u++) v[u] = __ldg(ue + (size_t)(s0 + u) * (N_DIM / 2));
        #pragma unroll
        for (int u = 0; u < 8; u++) {
            int s = sq * 32 + s0 + u;
            float2 f = __half22float2(v[u]);
            float wes = s_we[s], ves = s_ve[s];
            acc0 += tanh_fast(wes + f.x) * ves;
            acc1 += tanh_fast(wes + f.y) * ves;
        }
    }
    *(float2*)&s_part[sq * N_DIM + 2 * np] = make_float2(acc0, acc1);
    __syncthreads();

    float e = 0.0f;
    if (tid < N_DIM) {
        e = ve_b[0];
        #pragma unroll
        for (int q = 0; q < 4; q++) e += s_part[q * N_DIM + tid];
        red[tid] = e;
    }
    __syncthreads();
    for (int o = 128; o >= 32; o >>= 1) {
        if (tid < o) red[tid] = fmaxf(red[tid], red[tid + o]);
        __syncthreads();
    }
    if (tid < 32) {
        float v = red[tid];
        #pragma unroll
        for (int o = 16; o; o >>= 1) v = fmaxf(v, __shfl_xor_sync(0xffffffffu, v, o));
        red[tid] = v;
    }
    __syncthreads();
    float mx = red[0];
    float ev = 0.0f;
    __syncthreads();
    if (tid < N_DIM) {
        ev = __expf(e - mx);
        red[tid] = ev;
    }
    __syncthreads();
    for (int o = 128; o >= 32; o >>= 1) {
        if (tid < o) red[tid] += red[tid + o];
        __syncthreads();
    }
    if (tid < 32) {
        float v = red[tid];
        #pragma unroll
        for (int o = 16; o; o >>= 1) v += __shfl_xor_sync(0xffffffffu, v, o);
        red[tid] = v;
    }
    __syncthreads();
    if (tid < N_DIM) {
        float alpha = ev / red[0];
        g_xt[b * N_DIM + tid] = alpha * x[(size_t)t * B_DIM * N_DIM + b * N_DIM + tid];
    }
}

// ---------------- k_gatescell: tf32 gate GEMM (reg-prefetch pipeline) + cell + we ----
// grid (32, 4). Identical math to round 11; mainloop prefetches chunk q+1's global
// loads into registers before the MMA phase so LDG latency overlaps MMA.
__global__ void __launch_bounds__(256) k_gatescell(int t,
        const float* __restrict__ Wih, const float* __restrict__ Whh,
        const float* __restrict__ b_ih, const float* __restrict__ b_hh,
        const float* __restrict__ We_w) {
    __shared__ float pool[128 * 72];
    float* As = pool;
    float* Bs = pool + 128 * SPAD;
    int in = t & 1, ob = in ^ 1;
    const float* hin = g_hbuf[in];
    const float* cin = g_cbuf[in];
    float* hout = g_hbuf[ob];
    float* cout = g_cbuf[ob];
    int tid = threadIdx.x;
    int w = tid >> 5, lane = tid & 31;
    int g = lane >> 2, tig = lane & 3;
    int wm = w & 3, wn = w >> 2;
    int cb = blockIdx.x;
    int m0 = blockIdx.y * 128;
    int r = tid >> 3, kq = (tid & 7) * 4;
    float c[2][4][4] = {};
    float4 aReg[4], bReg[2];

    // prefetch chunk 0 (k0 = 0 -> xt / Wih)
    #pragma unroll
    for (int i = 0; i < 4; i++) {
        int row = r + 32 * i;
        aReg[i] = *(const float4*)(g_xt + (size_t)(m0 + row) * N_DIM + kq);
    }
    #pragma unroll
    for (int i2 = 0; i2 < 2; i2++) {
        int i = r + 32 * i2;
        int j = (i & 3) * M_DIM + cb * 16 + (i >> 2);
        bReg[i2] = *(const float4*)(Wih + (size_t)j * N_DIM + kq);
    }

    for (int q = 0; q < NCHUNK; q++) {
        #pragma unroll
        for (int i = 0; i < 4; i++)
            *(float4*)&As[(r + 32 * i) * SPAD + kq] = aReg[i];
        #pragma unroll
        for (int i2 = 0; i2 < 2; i2++)
            *(float4*)&Bs[(r + 32 * i2) * SPAD + kq] = bReg[i2];
        __syncthreads();

        // prefetch chunk q+1 (overlaps with MMA below)
        if (q < NCHUNK - 1) {
            int k0 = (q + 1) * 32;
            const float* asrc; int astride;
            if (k0 < N_DIM) { asrc = g_xt + k0; astride = N_DIM; }
            else            { asrc = hin + (k0 - N_DIM); astride = M_DIM; }
            #pragma unroll
            for (int i = 0; i < 4; i++) {
                int row = r + 32 * i;
                aReg[i] = *(const float4*)(asrc + (size_t)(m0 + row) * astride + kq);
            }
            #pragma unroll
            for (int i2 = 0; i2 < 2; i2++) {
                int i = r + 32 * i2;
                int j = (i & 3) * M_DIM + cb * 16 + (i >> 2);
                const float* bp = (k0 < N_DIM) ? (Wih + (size_t)j * N_DIM + k0)
                                               : (Whh + (size_t)j * M_DIM + (k0 - N_DIM));
                bReg[i2] = *(const float4*)(bp + kq);
            }
        }

        #pragma unroll
        for (int kt = 0; kt < 4; kt++) {
            int kk = kt * 8 + tig;
            uint32_t ahi[2][4], alo[2][4], bhi[4][2], blo[4][2];
            #pragma unroll
            for (int mt = 0; mt < 2; mt++) {
                int rb = wm * 32 + mt * 16 + g;
                tf32_split(As[rb * SPAD + kk],           ahi[mt][0], alo[mt][0]);
                tf32_split(As[(rb + 8) * SPAD + kk],     ahi[mt][1], alo[mt][1]);
                tf32_split(As[rb * SPAD + kk + 4],       ahi[mt][2], alo[mt][2]);
                tf32_split(As[(rb + 8) * SPAD + kk + 4], ahi[mt][3], alo[mt][3]);
            }
            #pragma unroll
            for (int nt = 0; nt < 4; nt++) {
                int nb = wn * 32 + nt * 8 + g;
                tf32_split(Bs[nb * SPAD + kk],     bhi[nt][0], blo[nt][0]);
                tf32_split(Bs[nb * SPAD + kk + 4], bhi[nt][1], blo[nt][1]);
            }
            #pragma unroll
            for (int mt = 0; mt < 2; mt++)
                #pragma unroll
                for (int nt = 0; nt < 4; nt++) {
                    mma_tf32(c[mt][nt], ahi[mt], bhi[nt]);
                    mma_tf32(c[mt][nt], ahi[mt], blo[nt]);
                    mma_tf32(c[mt][nt], alo[mt], bhi[nt]);
                }
        }
        __syncthreads();
    }

    // stage accumulators: pool[row][68]
    #pragma unroll
    for (int mt = 0; mt < 2; mt++) {
        int rl = wm * 32 + mt * 16 + g;
        #pragma unroll
        for (int nt = 0; nt < 4; nt++) {
            int qd = wn * 32 + nt * 8 + tig * 2;
            pool[rl * 68 + qd]           = c[mt][nt][0];
            pool[rl * 68 + qd + 1]       = c[mt][nt][1];
            pool[(rl + 8) * 68 + qd]     = c[mt][nt][2];
            pool[(rl + 8) * 68 + qd + 1] = c[mt][nt][3];
        }
    }
    __syncthreads();

    // cell
    float hnv[8], cnv[8];
    #pragma unroll
    for (int u = 0; u < 8; u++) {
        int idx = tid + 256 * u;
        int rl = idx >> 4, ml = idx & 15;
        int b = m0 + rl;
        int m = cb * 16 + ml;
        float gi = pool[rl * 68 + ml * 4 + 0] + b_ih[m]             + b_hh[m];
        float gf = pool[rl * 68 + ml * 4 + 1] + b_ih[M_DIM + m]     + b_hh[M_DIM + m];
        float gg = pool[rl * 68 + ml * 4 + 2] + b_ih[2 * M_DIM + m] + b_hh[2 * M_DIM + m];
        float go = pool[rl * 68 + ml * 4 + 3] + b_ih[3 * M_DIM + m] + b_hh[3 * M_DIM + m];
        float cprev = cin[(size_t)b * M_DIM + m];
        float si = sigmoid_fast(gi);
        float sf = sigmoid_fast(gf);
        float tg = tanh_fast(gg);
        float so = sigmoid_fast(go);
        float cn = sf * cprev + si * tg;
        float hn = so * tanh_fast(cn);
        cout[(size_t)b * M_DIM + m] = cn;
        hout[(size_t)b * M_DIM + m] = hn;
        g_hseq[(size_t)t * B_DIM * M_DIM + (size_t)b * M_DIM + m] = hn;
        hnv[u] = hn;
        cnv[u] = cn;
    }
    __syncthreads();

    if (t == T_DIM - 1) return;

    // we-partial epilogue
    float* s_hc = pool;
    float* s_We = pool + 128 * HCPAD;
    #pragma unroll
    for (int u = 0; u < 8; u++) {
        int idx = tid + 256 * u;
        int rl = idx >> 4, ml = idx & 15;
        s_hc[rl * HCPAD + ml]      = hnv[u];
        s_hc[rl * HCPAD + 16 + ml] = cnv[u];
    }
    for (int i = tid; i < 128 * 16; i += 256) {
        int s = i >> 4, kh = i & 15;
        s_We[s * HCPAD + kh]      = We_w[(size_t)s * 1024 + cb * 16 + kh];
        s_We[s * HCPAD + 16 + kh] = We_w[(size_t)s * 1024 + 512 + cb * 16 + kh];
    }
    __syncthreads();

    int tx = tid & 15, ty4 = tid >> 4;
    #pragma unroll
    for (int sub = 0; sub < 4; sub++) {
        int r0 = (sub & 1) * 64, s0 = (sub >> 1) * 64;
        float acc[4][4] = {};
        #pragma unroll
        for (int kk = 0; kk < 32; kk += 4) {
            float4 a4[4], b4[4];
            #pragma unroll
            for (int ii = 0; ii < 4; ii++)
                a4[ii] = *(const float4*)&s_hc[(r0 + ty4 * 4 + ii) * HCPAD + kk];
            #pragma unroll
            for (int jj = 0; jj < 4; jj++)
                b4[jj] = *(const float4*)&s_We[(s0 + tx * 4 + jj) * HCPAD + kk];
            #pragma unroll
            for (int ii = 0; ii < 4; ii++) {
                float av[4] = {a4[ii].x, a4[ii].y, a4[ii].z, a4[ii].w};
                #pragma unroll
                for (int jj = 0; jj < 4; jj++) {
                    acc[ii][jj] += av[0] * b4[jj].x + av[1] * b4[jj].y
                                 + av[2] * b4[jj].z + av[3] * b4[jj].w;
                }
            }
        }
        #pragma unroll
        for (int ii = 0; ii < 4; ii++) {
            int row = m0 + r0 + ty4 * 4 + ii;
            #pragma unroll
            for (int jj = 0; jj < 4; jj++)
                g_wepart[(cb * B_DIM + row) * T_DIM + s0 + tx * 4 + jj] = acc[ii][jj];
        }
    }
}

// ---------------- k_ud (tf32 2-term mma) ----------------
__global__ void __launch_bounds__(256) k_ud(
        const float* __restrict__ Ud_w, const float* __restrict__ Ud_b,
        const float* __restrict__ vd_w) {
    __shared__ float As[128 * SPAD];
    __shared__ float Bs[64 * SPAD];
    int tid = threadIdx.x;
    int w = tid >> 5, lane = tid & 31;
    int g = lane >> 2, tig = lane & 3;
    int wm = w & 3, wn = w >> 2;
    int m0 = blockIdx.y * 128, n0 = blockIdx.x * 64;
    int r = tid >> 3, kq = (tid & 7) * 4;
    float c[2][4][4] = {};

    for (int k0 = 0; k0 < M_DIM; k0 += 32) {
        #pragma unroll
        for (int i = 0; i < 4; i++) {
            int row = r + 32 * i;
            *(float4*)&As[row * SPAD + kq] =
                *(const float4*)(g_hseq + (size_t)(m0 + row) * M_DIM + k0 + kq);
        }
        #pragma unroll
        for (int i = 0; i < 2; i++) {
            int row = r + 32 * i;
            *(float4*)&Bs[row * SPAD + kq] =
                *(const float4*)(Ud_w + (size_t)(n0 + row) * M_DIM + k0 + kq);
        }
        __syncthreads();
        #pragma unroll
        for (int kt = 0; kt < 4; kt++) {
            int kk = kt * 8 + tig;
            uint32_t ahi[2][4], alo[2][4], bhi[4][2];
            #pragma unroll
            for (int mt = 0; mt < 2; mt++) {
                int rb = wm * 32 + mt * 16 + g;
                tf32_split(As[rb * SPAD + kk],           ahi[mt][0], alo[mt][0]);
                tf32_split(As[(rb + 8) * SPAD + kk],     ahi[mt][1], alo[mt][1]);
                tf32_split(As[rb * SPAD + kk + 4],       ahi[mt][2], alo[mt][2]);
                tf32_split(As[(rb + 8) * SPAD + kk + 4], ahi[mt][3], alo[mt][3]);
            }
            #pragma unroll
            for (int nt = 0; nt < 4; nt++) {
                int nb = wn * 32 + nt * 8 + g;
                bhi[nt][0] = tf32_hi(Bs[nb * SPAD + kk]);
                bhi[nt][1] = tf32_hi(Bs[nb * SPAD + kk + 4]);
            }
            #pragma unroll
            for (int mt = 0; mt < 2; mt++)
                #pragma unroll
                for (int nt = 0; nt < 4; nt++) {
                    mma_tf32(c[mt][nt], ahi[mt], bhi[nt]);
                    mma_tf32(c[mt][nt], alo[mt], bhi[nt]);
                }
        }
        __syncthreads();
    }
    #pragma unroll
    for (int mt = 0; mt < 2; mt++) {
        float rs0 = 0.0f, rs8 = 0.0f;
        #pragma unroll
        for (int nt = 0; nt < 4; nt++) {
            int j0 = n0 + wn * 32 + nt * 8 + tig * 2;
            float w0 = vd_w[j0], w1 = vd_w[j0 + 1];
            float d0 = Ud_b[j0], d1 = Ud_b[j0 + 1];
            rs0 += tanh_fast(c[mt][nt][0] + d0) * w0 + tanh_fast(c[mt][nt][1] + d1) * w1;
            rs8 += tanh_fast(c[mt][nt][2] + d0) * w0 + tanh_fast(c[mt][nt][3] + d1) * w1;
        }
        rs0 += __shfl_xor_sync(0xffffffffu, rs0, 1);
        rs0 += __shfl_xor_sync(0xffffffffu, rs0, 2);
        rs8 += __shfl_xor_sync(0xffffffffu, rs8, 1);
        rs8 += __shfl_xor_sync(0xffffffffu, rs8, 2);
        if (tig == 0) {
            int r0 = m0 + wm * 32 + mt * 16 + g;
            g_part[(size_t)r0 * 16 + blockIdx.x * 2 + wn] = rs0;
            g_part[(size_t)(r0 + 8) * 16 + blockIdx.x * 2 + wn] = rs8;
        }
    }
}

// ---------------- reduce 16 partials -> l[b][t] ----------------
__global__ void k_lred(const float* __restrict__ vd_b) {
    int r = blockIdx.x * 256 + threadIdx.x;
    const float4* p = (const float4*)(g_part + (size_t)r * 16);
    float tot = vd_b[0];
    #pragma unroll
    for (int i = 0; i < 4; i++) {
        float4 a = p[i];
        tot += a.x + a.y + a.z + a.w;
    }
    int tt = r >> 9;
    int b = r & 511;
    g_l[b * T_DIM + tt] = tot;
}

// ---------------- beta = softmax_t(l) -> out[512 + b*128 + t] ----------------
__global__ void k_beta(float* __restrict__ out) {
    __shared__ float red[128];
    int b = blockIdx.x;
    int tid = threadIdx.x;
    float v = g_l[b * T_DIM + tid];
    red[tid] = v;
    __syncthreads();
    for (int o = 64; o; o >>= 1) { if (tid < o) red[tid] = fmaxf(red[tid], red[tid + o]); __syncthreads(); }
    float mx = red[0];
    __syncthreads();
    float e = __expf(v - mx);
    red[tid] = e;
    __syncthreads();
    for (int o = 64; o; o >>= 1) { if (tid < o) red[tid] += red[tid + o]; __syncthreads(); }
    out[B_DIM + b * T_DIM + tid] = e / red[0];
}

// ---------------- ctx + logits fused ----------------
__global__ void k_out(float* __restrict__ out, const float* __restrict__ out_w,
                      const float* __restrict__ out_b) {
    __shared__ float s_beta[T_DIM];
    __shared__ float red[512];
    int b = blockIdx.x;
    int tid = threadIdx.x;
    if (tid < T_DIM) s_beta[tid] = out[B_DIM + b * T_DIM + tid];
    __syncthreads();
    float acc = 0.0f;
    #pragma unroll 4
    for (int tt = 0; tt < T_DIM; tt++)
        acc += s_beta[tt] * g_hseq[(size_t)tt * B_DIM * M_DIM + b * M_DIM + tid];
    red[tid] = acc * out_w[tid];
    __syncthreads();
    for (int o = 256; o; o >>= 1) { if (tid < o) red[tid] += red[tid + o]; __syncthreads(); }
    if (tid == 0) out[b] = red[0] + out_b[0];
}

// ---------------- host launcher ----------------
extern "C" void kernel_launch(void* const* d_in, const int* in_sizes, int n_in,
                              void* d_out, int out_size) {
    const float* x    = (const float*)d_in[0];
    const float* h0   = (const float*)d_in[1];
    const float* c0   = (const float*)d_in[2];
    const float* Wih  = (const float*)d_in[3];
    const float* Whh  = (const float*)d_in[4];
    const float* b_ih = (const float*)d_in[5];
    const float* b_hh = (const float*)d_in[6];
    const float* We_w = (const float*)d_in[7];
    const float* We_b = (const float*)d_in[8];
    const float* Ue_w = (const float*)d_in[9];
    const float* Ue_b = (const float*)d_in[10];
    const float* ve_w = (const float*)d_in[11];
    const float* ve_b = (const float*)d_in[12];
    const float* Ud_w = (const float*)d_in[13];
    const float* Ud_b = (const float*)d_in[14];
    const float* vd_w = (const float*)d_in[15];
    const float* vd_b = (const float*)d_in[16];
    const float* out_w = (const float*)d_in[17];
    const float* out_b = (const float*)d_in[18];
    float* out = (float*)d_out;

    k_init<<<B_DIM, M_DIM>>>(h0, c0);
    k_ue<<<dim3(B_DIM, N_DIM / 64), 256>>>(x, Ue_w, Ue_b);
    k_we<<<dim3(T_DIM / 64, B_DIM / 64, 8), 256>>>(We_w);
    for (int t = 0; t < T_DIM; t++) {
        k_e<<<B_DIM, 512>>>(t, x, We_b, ve_w, ve_b);
        k_gatescell<<<dim3(M_DIM / 16, B_DIM / 128), 256>>>(t, Wih, Whh, b_ih, b_hh, We_w);
    }
    k_ud<<<dim3(M_DIM / 64, (T_DIM * B_DIM) / 128), 256>>>(Ud_w, Ud_b, vd_w);
    k_lred<<<(T_DIM * B_DIM) / 256, 256>>>(vd_b);
    k_beta<<<B_DIM, T_DIM>>>(out);
    k_out<<<B_DIM, M_DIM>>>(out, out_w, out_b);
}